// round 8
// baseline (speedup 1.0000x reference)
#include <cuda_runtime.h>
#include <cuda_bf16.h>
#include <cstdint>

// Problem constants (B=2, T=512, C=256, HID=1024)
constexpr int Mrows = 1024;   // B*T
constexpr int Cdim  = 256;
constexpr int Hdim  = 1024;
constexpr int NBLK  = 128;    // persistent grid size (<= 148 SMs, all co-resident)
constexpr int NTHR  = 512;

// Static device scratch
__device__ __nv_bfloat16 g_h2 [Mrows * Cdim];
__device__ __nv_bfloat16 g_hid[Mrows * Hdim];
__device__ __nv_bfloat16 g_W1 [Hdim * Cdim];
__device__ __nv_bfloat16 g_W2 [Cdim * Hdim];
__device__ unsigned      g_bar[2];   // zero-init; monotonic ticket barriers

// ---------------------------------------------------------------------------
// PTX helpers
// ---------------------------------------------------------------------------
__device__ __forceinline__ uint32_t smem_u32(const void* p) {
    return (uint32_t)__cvta_generic_to_shared(p);
}
__device__ __forceinline__ void ldsm_x4(uint32_t& r0, uint32_t& r1,
                                        uint32_t& r2, uint32_t& r3, uint32_t a) {
    asm volatile("ldmatrix.sync.aligned.m8n8.x4.shared.b16 {%0,%1,%2,%3},[%4];"
                 : "=r"(r0), "=r"(r1), "=r"(r2), "=r"(r3) : "r"(a));
}
__device__ __forceinline__ void ldsm_x2(uint32_t& r0, uint32_t& r1, uint32_t a) {
    asm volatile("ldmatrix.sync.aligned.m8n8.x2.shared.b16 {%0,%1},[%2];"
                 : "=r"(r0), "=r"(r1) : "r"(a));
}
__device__ __forceinline__ void mma_bf16(float* c, const uint32_t* a, const uint32_t* b) {
    asm volatile(
        "mma.sync.aligned.m16n8k16.row.col.f32.bf16.bf16.f32 "
        "{%0,%1,%2,%3},{%4,%5,%6,%7},{%8,%9},{%0,%1,%2,%3};"
        : "+f"(c[0]), "+f"(c[1]), "+f"(c[2]), "+f"(c[3])
        : "r"(a[0]), "r"(a[1]), "r"(a[2]), "r"(a[3]), "r"(b[0]), "r"(b[1]));
}
__device__ __forceinline__ void cp_async16(uint32_t s, const void* g) {
    asm volatile("cp.async.cg.shared.global [%0], [%1], 16;" :: "r"(s), "l"(g));
}
__device__ __forceinline__ void cp_commit() {
    asm volatile("cp.async.commit_group;");
}
template <int N> __device__ __forceinline__ void cp_wait() {
    asm volatile("cp.async.wait_group %0;" :: "n"(N));
}

// Grid barrier: monotonic ticket, no reset needed across graph replays.
// Each launch consumes exactly one generation (NBLK tickets) per slot.
__device__ __forceinline__ void grid_barrier(int slot) {
    __threadfence();            // release this thread's prior writes
    __syncthreads();            // all block's writes done + fenced
    if (threadIdx.x == 0) {
        const unsigned ticket = atomicAdd(&g_bar[slot], 1u);
        const unsigned target = ticket - (ticket % NBLK) + NBLK;
        while (*(volatile unsigned*)&g_bar[slot] < target) { }
        __threadfence();        // acquire
    }
    __syncthreads();
}

// ---------------------------------------------------------------------------
// GEMM phase (device function): double-buffered cp.async bf16 HMMA.
//   C[m,n] = sum_k A[m,k]*B[n,k]   (A:[M,K], B:[N,K] bf16 row-major)
// MODE 0: relu(acc + bias[n]) -> bf16 Cout
// MODE 1: acc + resid[m,n] + bias[n] + bias2[n] -> fp32 Cout
// ---------------------------------------------------------------------------
template <int BM, int BN, int BK, int WARPS_M, int WARPS_N, int MODE>
__device__ __forceinline__ void gemm_phase(
    const __nv_bfloat16* __restrict__ A,
    const __nv_bfloat16* __restrict__ B,
    void* __restrict__ Cout,
    int Ktot, int Ntot, int m0, int n0,
    const float* __restrict__ bias,
    const float* __restrict__ resid,
    const float* __restrict__ bias2,
    char* smem)
{
    constexpr int NT  = WARPS_M * WARPS_N * 32;
    static_assert(NT == NTHR, "phase uses full block");
    constexpr int WM  = BM / WARPS_M;
    constexpr int WN  = BN / WARPS_N;
    constexpr int LDS = BK + 8;
    constexpr int MT  = WM / 16;
    constexpr int NTt = WN / 8;

    __nv_bfloat16* As = reinterpret_cast<__nv_bfloat16*>(smem);           // 2*BM*LDS
    __nv_bfloat16* Bs = As + 2 * BM * LDS;                                // 2*BN*LDS

    const int tid  = threadIdx.x;
    const int lane = tid & 31;
    const int warp = tid >> 5;
    const int wm   = warp / WARPS_N;
    const int wn   = warp % WARPS_N;
    const int kIters = Ktot / BK;

    auto load_stage = [&](int buf, int k0) {
        __nv_bfloat16* Ab = As + buf * BM * LDS;
        __nv_bfloat16* Bb = Bs + buf * BN * LDS;
        #pragma unroll
        for (int i = tid; i < BM * BK / 8; i += NT) {
            const int r = i / (BK / 8), cv = i % (BK / 8);
            cp_async16(smem_u32(&Ab[r * LDS + cv * 8]),
                       &A[(size_t)(m0 + r) * Ktot + k0 + cv * 8]);
        }
        #pragma unroll
        for (int i = tid; i < BN * BK / 8; i += NT) {
            const int r = i / (BK / 8), cv = i % (BK / 8);
            cp_async16(smem_u32(&Bb[r * LDS + cv * 8]),
                       &B[(size_t)(n0 + r) * Ktot + k0 + cv * 8]);
        }
        cp_commit();
    };

    float acc[MT][NTt][4];
    #pragma unroll
    for (int i = 0; i < MT; i++)
        #pragma unroll
        for (int j = 0; j < NTt; j++)
            #pragma unroll
            for (int r = 0; r < 4; r++) acc[i][j][r] = 0.f;

    load_stage(0, 0);

    for (int it = 0; it < kIters; it++) {
        const int buf = it & 1;
        if (it + 1 < kIters) {
            load_stage((it + 1) & 1, (it + 1) * BK);
            cp_wait<1>();
        } else {
            cp_wait<0>();
        }
        __syncthreads();

        const __nv_bfloat16* Ab = As + buf * BM * LDS;
        const __nv_bfloat16* Bb = Bs + buf * BN * LDS;

        #pragma unroll
        for (int ks = 0; ks < BK; ks += 16) {
            uint32_t afrag[MT][4];
            #pragma unroll
            for (int mt = 0; mt < MT; mt++) {
                const int row = wm * WM + mt * 16 + (lane & 15);
                const int col = ks + (lane >> 4) * 8;
                ldsm_x4(afrag[mt][0], afrag[mt][1], afrag[mt][2], afrag[mt][3],
                        smem_u32(&Ab[row * LDS + col]));
            }
            uint32_t bfrag[NTt][2];
            #pragma unroll
            for (int nt = 0; nt < NTt; nt++) {
                const int row = wn * WN + nt * 8 + (lane & 7);
                const int col = ks + ((lane >> 3) & 1) * 8;
                ldsm_x2(bfrag[nt][0], bfrag[nt][1],
                        smem_u32(&Bb[row * LDS + col]));
            }
            #pragma unroll
            for (int mt = 0; mt < MT; mt++)
                #pragma unroll
                for (int nt = 0; nt < NTt; nt++)
                    mma_bf16(acc[mt][nt], afrag[mt], bfrag[nt]);
        }
        __syncthreads();
    }

    // Epilogue
    #pragma unroll
    for (int mt = 0; mt < MT; mt++) {
        #pragma unroll
        for (int nt = 0; nt < NTt; nt++) {
            const int m = m0 + wm * WM + mt * 16 + (lane >> 2);
            const int n = n0 + wn * WN + nt * 8 + (lane & 3) * 2;
            float c0 = acc[mt][nt][0], c1 = acc[mt][nt][1];
            float c2 = acc[mt][nt][2], c3 = acc[mt][nt][3];
            if (MODE == 0) {
                const float b0 = bias[n], b1 = bias[n + 1];
                c0 = fmaxf(c0 + b0, 0.f); c1 = fmaxf(c1 + b1, 0.f);
                c2 = fmaxf(c2 + b0, 0.f); c3 = fmaxf(c3 + b1, 0.f);
                __nv_bfloat16* O = (__nv_bfloat16*)Cout;
                __nv_bfloat162 p;
                p.x = __float2bfloat16(c0); p.y = __float2bfloat16(c1);
                *reinterpret_cast<__nv_bfloat162*>(&O[(size_t)m * Ntot + n]) = p;
                p.x = __float2bfloat16(c2); p.y = __float2bfloat16(c3);
                *reinterpret_cast<__nv_bfloat162*>(&O[(size_t)(m + 8) * Ntot + n]) = p;
            } else {
                float* O = (float*)Cout;
                const float b0 = bias[n] + bias2[n];
                const float b1 = bias[n + 1] + bias2[n + 1];
                const float2 r0 = *reinterpret_cast<const float2*>(&resid[(size_t)m * Ntot + n]);
                const float2 r1 = *reinterpret_cast<const float2*>(&resid[(size_t)(m + 8) * Ntot + n]);
                float2 p;
                p.x = c0 + r0.x + b0; p.y = c1 + r0.y + b1;
                *reinterpret_cast<float2*>(&O[(size_t)m * Ntot + n]) = p;
                p.x = c2 + r1.x + b0; p.y = c3 + r1.y + b1;
                *reinterpret_cast<float2*>(&O[(size_t)(m + 8) * Ntot + n]) = p;
            }
        }
    }
}

// ===========================================================================
// Persistent fused kernel: phase A (convert + LN) | barrier | GEMM1 | barrier | GEMM2
// ===========================================================================
__global__ void __launch_bounds__(NTHR, 1)
block_fused(const float* __restrict__ x,
            const float* __restrict__ bp,
            const float* __restrict__ g2,
            const float* __restrict__ b2,
            const float* __restrict__ W1,
            const float* __restrict__ bf1,
            const float* __restrict__ W2,
            const float* __restrict__ bf2,
            float* __restrict__ out)
{
    extern __shared__ char smem[];
    const int bid  = blockIdx.x;
    const int tid  = threadIdx.x;
    const int lane = tid & 31;
    const int warp = tid >> 5;

    // ---------------- Phase A: weight convert + LN ----------------
    {
        // W1, W2 convert: 262144 floats each / 128 blocks = 2048 / 512 thr = 4 each
        const int i4 = bid * 2048 + tid * 4;
        {
            const float4 v = *reinterpret_cast<const float4*>(W1 + i4);
            __nv_bfloat162 p0, p1;
            p0.x = __float2bfloat16(v.x); p0.y = __float2bfloat16(v.y);
            p1.x = __float2bfloat16(v.z); p1.y = __float2bfloat16(v.w);
            reinterpret_cast<__nv_bfloat162*>(g_W1 + i4)[0] = p0;
            reinterpret_cast<__nv_bfloat162*>(g_W1 + i4)[1] = p1;
        }
        {
            const float4 v = *reinterpret_cast<const float4*>(W2 + i4);
            __nv_bfloat162 p0, p1;
            p0.x = __float2bfloat16(v.x); p0.y = __float2bfloat16(v.y);
            p1.x = __float2bfloat16(v.z); p1.y = __float2bfloat16(v.w);
            reinterpret_cast<__nv_bfloat162*>(g_W2 + i4)[0] = p0;
            reinterpret_cast<__nv_bfloat162*>(g_W2 + i4)[1] = p1;
        }
        // LN: warps 0..7 each handle one row (8 rows per block)
        if (warp < 8) {
            const int row = bid * 8 + warp;
            const int c0  = lane * 8;
            const float* rp = x + (size_t)row * Cdim + c0;
            float v[8];
            {
                const float4 a  = *reinterpret_cast<const float4*>(rp);
                const float4 b  = *reinterpret_cast<const float4*>(rp + 4);
                const float4 pa = *reinterpret_cast<const float4*>(bp + c0);
                const float4 pb = *reinterpret_cast<const float4*>(bp + c0 + 4);
                v[0] = a.x + pa.x; v[1] = a.y + pa.y; v[2] = a.z + pa.z; v[3] = a.w + pa.w;
                v[4] = b.x + pb.x; v[5] = b.y + pb.y; v[6] = b.z + pb.z; v[7] = b.w + pb.w;
            }
            float s = 0.f, q = 0.f;
            #pragma unroll
            for (int j = 0; j < 8; j++) { s += v[j]; q += v[j] * v[j]; }
            #pragma unroll
            for (int o = 16; o > 0; o >>= 1) {
                s += __shfl_xor_sync(0xffffffffu, s, o);
                q += __shfl_xor_sync(0xffffffffu, q, o);
            }
            const float mean = s * (1.0f / Cdim);
            const float var  = q * (1.0f / Cdim) - mean * mean;
            const float inv  = rsqrtf(var + 1e-5f);

            const float4 ga = *reinterpret_cast<const float4*>(g2 + c0);
            const float4 gb = *reinterpret_cast<const float4*>(g2 + c0 + 4);
            const float4 ba = *reinterpret_cast<const float4*>(b2 + c0);
            const float4 bb = *reinterpret_cast<const float4*>(b2 + c0 + 4);
            const float gg[8]  = {ga.x, ga.y, ga.z, ga.w, gb.x, gb.y, gb.z, gb.w};
            const float bbv[8] = {ba.x, ba.y, ba.z, ba.w, bb.x, bb.y, bb.z, bb.w};

            __nv_bfloat162 o2[4];
            #pragma unroll
            for (int j = 0; j < 4; j++) {
                o2[j].x = __float2bfloat16((v[2*j]   - mean) * inv * gg[2*j]   + bbv[2*j]);
                o2[j].y = __float2bfloat16((v[2*j+1] - mean) * inv * gg[2*j+1] + bbv[2*j+1]);
            }
            *reinterpret_cast<uint4*>(&g_h2[(size_t)row * Cdim + c0]) =
                *reinterpret_cast<uint4*>(o2);
        }
    }

    grid_barrier(0);

    // ---------------- Phase B: GEMM1  hid = relu(h2 @ W1^T + bf1) ----------
    // M=1024 N=1024 K=256; tile 64x128, warps 2x8; block -> (m=bid>>3, n=bid&7)
    gemm_phase<64, 128, 64, 2, 8, 0>(
        g_h2, g_W1, g_hid, Cdim, Hdim,
        (bid >> 3) * 64, (bid & 7) * 128,
        bf1, nullptr, nullptr, smem);

    grid_barrier(1);

    // ---------------- Phase C: GEMM2  out = hid @ W2^T + x + bp + bf2 ------
    // M=1024 N=256 K=1024; tile 64x32, warps 4x4; block -> (m=bid>>3, n=bid&7)
    gemm_phase<64, 32, 128, 4, 4, 1>(
        g_hid, g_W2, out, Hdim, Cdim,
        (bid >> 3) * 64, (bid & 7) * 32,
        bp, x, bf2, smem);
}

// ---------------------------------------------------------------------------
// Attention branch is exactly 0 (transform *= 0.0)  =>  sa == bp.
//   y = (x + bp) + relu(LN(x+bp)@W1^T + bf1) @ W2^T + bf2
// Inputs: 0:x 1:Wt 2:Wp 3:bp 4:g1 5:b1 6:g2 7:b2 8:W1 9:bf1 10:W2 11:bf2
// ---------------------------------------------------------------------------
extern "C" void kernel_launch(void* const* d_in, const int* in_sizes, int n_in,
                              void* d_out, int out_size)
{
    const float* x   = (const float*)d_in[0];
    const float* bp  = (const float*)d_in[3];
    const float* g2  = (const float*)d_in[6];
    const float* b2  = (const float*)d_in[7];
    const float* W1  = (const float*)d_in[8];
    const float* bf1 = (const float*)d_in[9];
    const float* W2  = (const float*)d_in[10];
    const float* bf2 = (const float*)d_in[11];
    float* out = (float*)d_out;

    // smem = max(GEMM1, GEMM2) stage memory:
    //   GEMM1: 2*(64*72 + 128*72)*2 = 55296 B
    //   GEMM2: 2*(64*136 + 32*136)*2 = 52224 B
    constexpr int SMEM = 2 * (64 * 72 + 128 * 72) * 2;
    cudaFuncSetAttribute(block_fused,
                         cudaFuncAttributeMaxDynamicSharedMemorySize, SMEM);

    block_fused<<<NBLK, NTHR, SMEM>>>(x, bp, g2, b2, W1, bf1, W2, bf2, out);
}